// round 1
// baseline (speedup 1.0000x reference)
#include <cuda_runtime.h>
#include <math_constants.h>

// Problem constants (fixed shapes from setup_inputs)
#define BB   8      // batch
#define NPTS 256    // N = 4096/16
#define BETA 192    // 0.75*N
#define KN   768    // 3*N oversampled points
#define CO   128    // out channels
#define HO   256
#define WO   256
#define CF   64     // res2 channels
#define HF   512
#define WF   512

__device__ float g_unc[BB * KN];

// merge running top2 (m1>=m2) with another pair (o1>=o2)
__device__ __forceinline__ void merge2(float &m1, float &m2, float o1, float o2) {
    float n1 = fmaxf(m1, o1);
    float n2 = fmaxf(fminf(m1, o1), fmaxf(m2, o2));
    m1 = n1; m2 = n2;
}

// ---------------------------------------------------------------------------
// Kernel 1: per-point uncertainty = bilinear( top2 - top1 over 128 channels )
// one warp per (batch, oversampled point)
// ---------------------------------------------------------------------------
__global__ void uncert_kernel(const float* __restrict__ outm,
                              const float* __restrict__ rand_over) {
    int warp = (blockIdx.x * blockDim.x + threadIdx.x) >> 5;
    int lane = threadIdx.x & 31;
    if (warp >= BB * KN) return;
    int b = warp / KN;
    int p = warp - b * KN;

    float px = rand_over[(b * KN + p) * 2 + 0];
    float py = rand_over[(b * KN + p) * 2 + 1];
    // align_corners=False mapping: pixel = p*size - 0.5
    float gx = px * (float)WO - 0.5f;
    float gy = py * (float)HO - 0.5f;
    float x0f = floorf(gx), y0f = floorf(gy);
    float wx = gx - x0f, wy = gy - y0f;
    int x0 = (int)x0f, y0 = (int)y0f;

    const float* base = outm + (long long)b * CO * HO * WO;
    bool xv0 = (x0 >= 0) && (x0 < WO);
    bool xv1 = (x0 + 1 >= 0) && (x0 + 1 < WO);
    int xc0 = min(max(x0, 0), WO - 1);
    int xc1 = min(max(x0 + 1, 0), WO - 1);

    float unc = 0.f;
#pragma unroll
    for (int ry = 0; ry < 2; ry++) {
        int y = y0 + ry;
        bool yv = (y >= 0) && (y < HO);
        int yc = min(max(y, 0), HO - 1);
        const float* rp = base + yc * WO;

        float a1 = -CUDART_INF_F, a2 = -CUDART_INF_F;   // corner (y, x0)
        float c1 = -CUDART_INF_F, c2 = -CUDART_INF_F;   // corner (y, x0+1)
#pragma unroll
        for (int cc = 0; cc < CO / 32; cc++) {
            int ch = lane + cc * 32;
            const float* cp = rp + (long long)ch * (HO * WO);
            float va = __ldg(cp + xc0);
            float vb = __ldg(cp + xc1);
            // insert single value into running top2
            merge2(a1, a2, va, -CUDART_INF_F);
            merge2(c1, c2, vb, -CUDART_INF_F);
        }
#pragma unroll
        for (int off = 16; off; off >>= 1) {
            merge2(a1, a2, __shfl_xor_sync(0xFFFFFFFFu, a1, off),
                           __shfl_xor_sync(0xFFFFFFFFu, a2, off));
            merge2(c1, c2, __shfl_xor_sync(0xFFFFFFFFu, c1, off),
                           __shfl_xor_sync(0xFFFFFFFFu, c2, off));
        }
        float da = (yv && xv0) ? (a2 - a1) : 0.f;  // = -(top1 - top2), zero-padded
        float db = (yv && xv1) ? (c2 - c1) : 0.f;
        float wyr = ry ? wy : (1.f - wy);
        unc += wyr * ((1.f - wx) * da + wx * db);
    }
    if (lane == 0) g_unc[b * KN + p] = unc;
}

// ---------------------------------------------------------------------------
// Kernel 2: exact top-192 (descending value, ascending index on ties) per batch
// bitonic sort of 1024 64-bit keys; then build points[B,256,2]
// ---------------------------------------------------------------------------
__global__ void topk_kernel(const float* __restrict__ rand_over,
                            const float* __restrict__ rand_cov,
                            float* __restrict__ points) {
    int b = blockIdx.x;
    int t = threadIdx.x;
    __shared__ unsigned long long keys[1024];

    unsigned long long key = 0ull;  // pad: sorts last (all real keys have high word > 0)
    if (t < KN) {
        float u = g_unc[b * KN + t];
        unsigned ub = __float_as_uint(u);
        ub = (ub & 0x80000000u) ? ~ub : (ub | 0x80000000u);  // total order, ascending
        key = ((unsigned long long)ub << 32) | (unsigned long long)(0xFFFFFFFFu - (unsigned)t);
    }
    keys[t] = key;
    __syncthreads();

    for (int k = 2; k <= 1024; k <<= 1) {
        for (int j = k >> 1; j > 0; j >>= 1) {
            int ixj = t ^ j;
            if (ixj > t) {
                unsigned long long A = keys[t], Bv = keys[ixj];
                bool sw = ((t & k) == 0) ? (A < Bv) : (A > Bv);  // overall descending
                if (sw) { keys[t] = Bv; keys[ixj] = A; }
            }
            __syncthreads();
        }
    }

    if (t < BETA) {
        unsigned idx = 0xFFFFFFFFu - (unsigned)(keys[t] & 0xFFFFFFFFull);
        points[(b * NPTS + t) * 2 + 0] = rand_over[(b * KN + idx) * 2 + 0];
        points[(b * NPTS + t) * 2 + 1] = rand_over[(b * KN + idx) * 2 + 1];
    } else if (t < NPTS) {
        int i = t - BETA;
        points[(b * NPTS + t) * 2 + 0] = rand_cov[(b * (NPTS - BETA) + i) * 2 + 0];
        points[(b * NPTS + t) * 2 + 1] = rand_cov[(b * (NPTS - BETA) + i) * 2 + 1];
    }
}

// ---------------------------------------------------------------------------
// Kernel 3: gather coarse(128ch)+fine(64ch) features at point, then 128x192 dot
// one block per (batch, point), 128 threads
// ---------------------------------------------------------------------------
__device__ __forceinline__ float bilerp_sample(const float* __restrict__ base,
                                               int H, int W, float px, float py) {
    float gx = px * (float)W - 0.5f;
    float gy = py * (float)H - 0.5f;
    float x0f = floorf(gx), y0f = floorf(gy);
    float wx = gx - x0f, wy = gy - y0f;
    int x0 = (int)x0f, y0 = (int)y0f;
    bool xv0 = (x0 >= 0) && (x0 < W);
    bool xv1 = (x0 + 1 >= 0) && (x0 + 1 < W);
    bool yv0 = (y0 >= 0) && (y0 < H);
    bool yv1 = (y0 + 1 >= 0) && (y0 + 1 < H);
    int xc0 = min(max(x0, 0), W - 1);
    int xc1 = min(max(x0 + 1, 0), W - 1);
    int yc0 = min(max(y0, 0), H - 1);
    int yc1 = min(max(y0 + 1, 0), H - 1);
    float v00 = (yv0 && xv0) ? __ldg(base + yc0 * W + xc0) : 0.f;
    float v01 = (yv0 && xv1) ? __ldg(base + yc0 * W + xc1) : 0.f;
    float v10 = (yv1 && xv0) ? __ldg(base + yc1 * W + xc0) : 0.f;
    float v11 = (yv1 && xv1) ? __ldg(base + yc1 * W + xc1) : 0.f;
    return v00 * (1.f - wx) * (1.f - wy) + v01 * wx * (1.f - wy)
         + v10 * (1.f - wx) * wy + v11 * wx * wy;
}

__global__ void render_kernel(const float* __restrict__ outm,
                              const float* __restrict__ res2,
                              const float* __restrict__ weight,
                              const float* __restrict__ bias,
                              const float* __restrict__ points,
                              float* __restrict__ rend) {
    __shared__ __align__(16) float feat[CO + CF];
    int bp = blockIdx.x;
    int b = bp / NPTS;
    int n = bp - b * NPTS;
    int t = threadIdx.x;

    float px = points[(b * NPTS + n) * 2 + 0];
    float py = points[(b * NPTS + n) * 2 + 1];

    // coarse: channel t of out
    {
        const float* base = outm + ((long long)(b * CO + t)) * (HO * WO);
        feat[t] = bilerp_sample(base, HO, WO, px, py);
    }
    // fine: channel t of res2 (first 64 threads)
    if (t < CF) {
        const float* base = res2 + ((long long)(b * CF + t)) * (HF * WF);
        feat[CO + t] = bilerp_sample(base, HF, WF, px, py);
    }
    __syncthreads();

    float acc = bias[t];
    const float4* wr = reinterpret_cast<const float4*>(weight + t * (CO + CF));
    const float4* fr = reinterpret_cast<const float4*>(feat);
#pragma unroll
    for (int i = 0; i < (CO + CF) / 4; i++) {
        float4 w4 = __ldg(&wr[i]);
        float4 f4 = fr[i];
        acc += w4.x * f4.x + w4.y * f4.y + w4.z * f4.z + w4.w * f4.w;
    }
    rend[((long long)b * CO + t) * NPTS + n] = acc;
}

// ---------------------------------------------------------------------------
// Launch
// ---------------------------------------------------------------------------
extern "C" void kernel_launch(void* const* d_in, const int* in_sizes, int n_in,
                              void* d_out, int out_size) {
    // metadata order: x, res2, out, rand_over, rand_cov, weight, bias
    const float* res2      = (const float*)d_in[1];
    const float* outm      = (const float*)d_in[2];
    const float* rand_over = (const float*)d_in[3];
    const float* rand_cov  = (const float*)d_in[4];
    const float* weight    = (const float*)d_in[5];
    const float* bias      = (const float*)d_in[6];

    float* rend   = (float*)d_out;                       // [B,128,256]
    float* points = (float*)d_out + BB * CO * NPTS;      // [B,256,2]

    // 1 warp per oversampled point: 8*768 = 6144 warps, 8 warps/block
    uncert_kernel<<<(BB * KN) / 8, 256>>>(outm, rand_over);
    // 1 block per batch
    topk_kernel<<<BB, 1024>>>(rand_over, rand_cov, points);
    // 1 block per (batch, point)
    render_kernel<<<BB * NPTS, 128>>>(outm, res2, weight, bias, points, rend);
}

// round 3
// speedup vs baseline: 1.7757x; 1.7757x over previous
#include <cuda_runtime.h>
#include <math_constants.h>

// Problem constants (fixed shapes from setup_inputs)
#define BB   8      // batch
#define NPTS 256    // N = 4096/16
#define BETA 192    // 0.75*N
#define KN   768    // 3*N oversampled points
#define CO   128    // out channels
#define HO   256
#define WO   256
#define CF   64     // res2 channels
#define HF   512
#define WF   512
#define CFEAT (CO + CF)   // 192

__device__ float g_unc[BB * KN];
__device__ __align__(16) float g_feat[BB * NPTS * CFEAT];   // [B, N, 192]

// merge running top2 (m1>=m2) with single value v
__device__ __forceinline__ void merge1(float &m1, float &m2, float v) {
    float n1 = fmaxf(m1, v);
    m2 = fmaxf(fminf(m1, v), m2);
    m1 = n1;
}
// merge running top2 with another pair (o1>=o2)
__device__ __forceinline__ void merge2(float &m1, float &m2, float o1, float o2) {
    float n1 = fmaxf(m1, o1);
    float n2 = fmaxf(fminf(m1, o1), fmaxf(m2, o2));
    m1 = n1; m2 = n2;
}

// ---------------------------------------------------------------------------
// Kernel 1: per-point uncertainty = bilinear( -(top1-top2) over 128 channels )
// one warp per (batch, oversampled point); all 16 loads batched up front
// ---------------------------------------------------------------------------
__global__ void uncert_kernel(const float* __restrict__ outm,
                              const float* __restrict__ rand_over) {
    int warp = (blockIdx.x * blockDim.x + threadIdx.x) >> 5;
    int lane = threadIdx.x & 31;
    if (warp >= BB * KN) return;
    int b = warp / KN;
    int p = warp - b * KN;

    float px = rand_over[(b * KN + p) * 2 + 0];
    float py = rand_over[(b * KN + p) * 2 + 1];
    float gx = px * (float)WO - 0.5f;
    float gy = py * (float)HO - 0.5f;
    float x0f = floorf(gx), y0f = floorf(gy);
    float wx = gx - x0f, wy = gy - y0f;
    int x0 = (int)x0f, y0 = (int)y0f;

    const float* base = outm + (long long)b * CO * HO * WO;
    bool xv0 = (x0 >= 0) && (x0 < WO);
    bool xv1 = (x0 + 1 >= 0) && (x0 + 1 < WO);
    bool yv0 = (y0 >= 0) && (y0 < HO);
    bool yv1 = (y0 + 1 >= 0) && (y0 + 1 < HO);
    int xc0 = min(max(x0, 0), WO - 1);
    int xc1 = min(max(x0 + 1, 0), WO - 1);
    int yc0 = min(max(y0, 0), HO - 1);
    int yc1 = min(max(y0 + 1, 0), HO - 1);

    const float* r0 = base + yc0 * WO;
    const float* r1 = base + yc1 * WO;

    // batch all 16 loads (2 rows x 2 corners x 4 channel chunks) for max MLP
    float v00[4], v01[4], v10[4], v11[4];
#pragma unroll
    for (int cc = 0; cc < 4; cc++) {
        long long co = (long long)(lane + cc * 32) * (HO * WO);
        v00[cc] = __ldg(r0 + co + xc0);
        v01[cc] = __ldg(r0 + co + xc1);
        v10[cc] = __ldg(r1 + co + xc0);
        v11[cc] = __ldg(r1 + co + xc1);
    }

    float a1 = -CUDART_INF_F, a2 = -CUDART_INF_F;   // (y0,   x0)
    float b1 = -CUDART_INF_F, b2 = -CUDART_INF_F;   // (y0,   x0+1)
    float c1 = -CUDART_INF_F, c2 = -CUDART_INF_F;   // (y0+1, x0)
    float d1 = -CUDART_INF_F, d2 = -CUDART_INF_F;   // (y0+1, x0+1)
#pragma unroll
    for (int cc = 0; cc < 4; cc++) {
        merge1(a1, a2, v00[cc]);
        merge1(b1, b2, v01[cc]);
        merge1(c1, c2, v10[cc]);
        merge1(d1, d2, v11[cc]);
    }
#pragma unroll
    for (int off = 16; off; off >>= 1) {
        merge2(a1, a2, __shfl_xor_sync(0xFFFFFFFFu, a1, off),
                       __shfl_xor_sync(0xFFFFFFFFu, a2, off));
        merge2(b1, b2, __shfl_xor_sync(0xFFFFFFFFu, b1, off),
                       __shfl_xor_sync(0xFFFFFFFFu, b2, off));
        merge2(c1, c2, __shfl_xor_sync(0xFFFFFFFFu, c1, off),
                       __shfl_xor_sync(0xFFFFFFFFu, c2, off));
        merge2(d1, d2, __shfl_xor_sync(0xFFFFFFFFu, d1, off),
                       __shfl_xor_sync(0xFFFFFFFFu, d2, off));
    }
    float e00 = (yv0 && xv0) ? (a2 - a1) : 0.f;   // -(top1 - top2), zero padded
    float e01 = (yv0 && xv1) ? (b2 - b1) : 0.f;
    float e10 = (yv1 && xv0) ? (c2 - c1) : 0.f;
    float e11 = (yv1 && xv1) ? (d2 - d1) : 0.f;
    float unc = (1.f - wy) * ((1.f - wx) * e00 + wx * e01)
              +        wy  * ((1.f - wx) * e10 + wx * e11);
    if (lane == 0) g_unc[b * KN + p] = unc;
}

// ---------------------------------------------------------------------------
// Kernel 2: exact top-192 per batch; register-resident bitonic, shfl stages
// ---------------------------------------------------------------------------
__global__ void topk_kernel(const float* __restrict__ rand_over,
                            const float* __restrict__ rand_cov,
                            float* __restrict__ points) {
    int b = blockIdx.x;
    int t = threadIdx.x;
    __shared__ unsigned long long sk[1024];

    unsigned long long key = 0ull;  // pad: sorts last (real keys have high word > 0)
    if (t < KN) {
        float u = g_unc[b * KN + t];
        unsigned ub = __float_as_uint(u);
        ub = (ub & 0x80000000u) ? ~ub : (ub | 0x80000000u);  // total order
        key = ((unsigned long long)ub << 32) | (unsigned long long)(0xFFFFFFFFu - (unsigned)t);
    }

    for (int k = 2; k <= 1024; k <<= 1) {
        for (int j = k >> 1; j; j >>= 1) {
            unsigned long long other;
            if (j >= 32) {
                __syncthreads();
                sk[t] = key;
                __syncthreads();
                other = sk[t ^ j];
            } else {
                other = __shfl_xor_sync(0xFFFFFFFFu, key, j);
            }
            bool iLower = ((t & j) == 0);
            bool desc   = ((t & k) == 0);
            unsigned long long mx = (key > other) ? key : other;
            unsigned long long mn = (key > other) ? other : key;
            key = (desc == iLower) ? mx : mn;   // overall descending
        }
    }

    if (t < BETA) {
        unsigned idx = 0xFFFFFFFFu - (unsigned)(key & 0xFFFFFFFFull);
        points[(b * NPTS + t) * 2 + 0] = rand_over[(b * KN + idx) * 2 + 0];
        points[(b * NPTS + t) * 2 + 1] = rand_over[(b * KN + idx) * 2 + 1];
    } else if (t < NPTS) {
        int i = t - BETA;
        points[(b * NPTS + t) * 2 + 0] = rand_cov[(b * (NPTS - BETA) + i) * 2 + 0];
        points[(b * NPTS + t) * 2 + 1] = rand_cov[(b * (NPTS - BETA) + i) * 2 + 1];
    }
}

// ---------------------------------------------------------------------------
// Kernel 3: gather coarse(128) + fine(64) features at each selected point
// one block per (batch, point), 192 threads; writes g_feat[B,N,192]
// ---------------------------------------------------------------------------
__device__ __forceinline__ float bilerp_sample(const float* __restrict__ base,
                                               int H, int W, float px, float py) {
    float gx = px * (float)W - 0.5f;
    float gy = py * (float)H - 0.5f;
    float x0f = floorf(gx), y0f = floorf(gy);
    float wx = gx - x0f, wy = gy - y0f;
    int x0 = (int)x0f, y0 = (int)y0f;
    bool xv0 = (x0 >= 0) && (x0 < W);
    bool xv1 = (x0 + 1 >= 0) && (x0 + 1 < W);
    bool yv0 = (y0 >= 0) && (y0 < H);
    bool yv1 = (y0 + 1 >= 0) && (y0 + 1 < H);
    int xc0 = min(max(x0, 0), W - 1);
    int xc1 = min(max(x0 + 1, 0), W - 1);
    int yc0 = min(max(y0, 0), H - 1);
    int yc1 = min(max(y0 + 1, 0), H - 1);
    float v00 = (yv0 && xv0) ? __ldg(base + yc0 * W + xc0) : 0.f;
    float v01 = (yv0 && xv1) ? __ldg(base + yc0 * W + xc1) : 0.f;
    float v10 = (yv1 && xv0) ? __ldg(base + yc1 * W + xc0) : 0.f;
    float v11 = (yv1 && xv1) ? __ldg(base + yc1 * W + xc1) : 0.f;
    return v00 * (1.f - wx) * (1.f - wy) + v01 * wx * (1.f - wy)
         + v10 * (1.f - wx) * wy + v11 * wx * wy;
}

__global__ void gather_kernel(const float* __restrict__ outm,
                              const float* __restrict__ res2,
                              const float* __restrict__ points) {
    int bp = blockIdx.x;
    int b = bp / NPTS;
    int n = bp - b * NPTS;
    int t = threadIdx.x;

    float px = points[(b * NPTS + n) * 2 + 0];
    float py = points[(b * NPTS + n) * 2 + 1];

    float v;
    if (t < CO) {
        const float* base = outm + ((long long)(b * CO + t)) * (HO * WO);
        v = bilerp_sample(base, HO, WO, px, py);
    } else {
        const float* base = res2 + ((long long)(b * CF + (t - CO))) * (HF * WF);
        v = bilerp_sample(base, HF, WF, px, py);
    }
    g_feat[(bp) * CFEAT + t] = v;
}

// ---------------------------------------------------------------------------
// Kernel 4: rend[b,o,n] = weight[o,:] . feat[b,n,:] + bias[o]
// block = 16 points x 128 out channels; feat tile in smem, weight streamed once
// ---------------------------------------------------------------------------
#define PTS_PER_BLK 16
__global__ void gemm_kernel(const float* __restrict__ weight,
                            const float* __restrict__ bias,
                            float* __restrict__ rend) {
    __shared__ __align__(16) float fs[PTS_PER_BLK * CFEAT];   // 12 KB
    int blk = blockIdx.x;
    int b  = blk / (NPTS / PTS_PER_BLK);
    int n0 = (blk % (NPTS / PTS_PER_BLK)) * PTS_PER_BLK;
    int t = threadIdx.x;

    const float4* fg = reinterpret_cast<const float4*>(g_feat + ((long long)b * NPTS + n0) * CFEAT);
    float4* fsm = reinterpret_cast<float4*>(fs);
#pragma unroll
    for (int i = t; i < PTS_PER_BLK * CFEAT / 4; i += 128)
        fsm[i] = fg[i];
    __syncthreads();

    float acc[PTS_PER_BLK];
    float bv = bias[t];
#pragma unroll
    for (int p = 0; p < PTS_PER_BLK; p++) acc[p] = bv;

    const float4* wr = reinterpret_cast<const float4*>(weight + t * CFEAT);
#pragma unroll
    for (int i = 0; i < CFEAT / 4; i++) {
        float4 w4 = __ldg(&wr[i]);
#pragma unroll
        for (int p = 0; p < PTS_PER_BLK; p++) {
            float4 f4 = fsm[p * (CFEAT / 4) + i];
            acc[p] += w4.x * f4.x + w4.y * f4.y + w4.z * f4.z + w4.w * f4.w;
        }
    }
#pragma unroll
    for (int p = 0; p < PTS_PER_BLK; p++)
        rend[((long long)b * CO + t) * NPTS + n0 + p] = acc[p];
}

// ---------------------------------------------------------------------------
// Launch
// ---------------------------------------------------------------------------
extern "C" void kernel_launch(void* const* d_in, const int* in_sizes, int n_in,
                              void* d_out, int out_size) {
    // metadata order: x, res2, out, rand_over, rand_cov, weight, bias
    const float* res2      = (const float*)d_in[1];
    const float* outm      = (const float*)d_in[2];
    const float* rand_over = (const float*)d_in[3];
    const float* rand_cov  = (const float*)d_in[4];
    const float* weight    = (const float*)d_in[5];
    const float* bias      = (const float*)d_in[6];

    float* rend   = (float*)d_out;                       // [B,128,256]
    float* points = (float*)d_out + BB * CO * NPTS;      // [B,256,2]

    uncert_kernel<<<(BB * KN) / 8, 256>>>(outm, rand_over);
    topk_kernel<<<BB, 1024>>>(rand_over, rand_cov, points);
    gather_kernel<<<BB * NPTS, CFEAT>>>(outm, res2, points);
    gemm_kernel<<<BB * (NPTS / PTS_PER_BLK), 128>>>(weight, bias, rend);
}